// round 15
// baseline (speedup 1.0000x reference)
#include <cuda_runtime.h>
#include <stdint.h>
#include <math.h>

#define BATCH 1024
#define DIM   128
#define N0    25
#define NPB   250
#define ROWS_T 276                 // 250 leaf + 25 idx1 + 1 root
#define FUSE_BLOCKS 32
#define FUSE_DONE FUSE_BLOCKS
#define CHUNK 48                   // rows per TMA chunk (24 KB)
#define NCHG  6                    // 5x48 + 36

// Dynamic smem layout (bytes)
#define OFF_BUF0 0
#define OFF_BUF1 24576
#define OFF_ROWS 49152             // 276 ints
#define OFF_ACT  50304             // 384 floats
#define OFF_REDM 51840             // 1024 floats (scratch + MLP reduce)
#define OFF_MBAR 55936             // 2 x u64
#define SMEM_BYTES 56320

// Fused weight: rows 0..127 = W0[0:128,:] ; rows 128..383 = W1 @ W0[128:256,:]
__device__ __align__(16) float g_Wf[384 * 128];
__device__ int g_flag;             // monotonic across replays (benign: Wf replay-invariant)

__device__ __forceinline__ uint32_t smem_u32(const void* p) {
    uint32_t a;
    asm("{ .reg .u64 t; cvta.to.shared.u64 t, %1; cvt.u32.u64 %0, t; }"
        : "=r"(a) : "l"(p));
    return a;
}
__device__ __forceinline__ void mbar_init(uint32_t mbar) {
    asm volatile("mbarrier.init.shared.b64 [%0], 1;" :: "r"(mbar) : "memory");
}
__device__ __forceinline__ void mbar_expect_tx(uint32_t mbar, uint32_t bytes) {
    asm volatile("mbarrier.arrive.expect_tx.shared.b64 _, [%0], %1;"
                 :: "r"(mbar), "r"(bytes) : "memory");
}
__device__ __forceinline__ void tma_bulk_row(uint32_t dst, const void* src, uint32_t mbar) {
    asm volatile(
        "cp.async.bulk.shared::cluster.global.mbarrier::complete_tx::bytes "
        "[%0], [%1], 512, [%2];"
        :: "r"(dst), "l"(src), "r"(mbar) : "memory");
}
__device__ __forceinline__ void mbar_wait(uint32_t mbar, uint32_t phase) {
    asm volatile(
        "{\n\t"
        ".reg .pred P;\n\t"
        "W_%=:\n\t"
        "mbarrier.try_wait.parity.shared::cta.b64 P, [%0], %1;\n\t"
        "@!P bra W_%=;\n\t"
        "}"
        :: "r"(mbar), "r"(phase) : "memory");
}
__device__ __forceinline__ void fence_proxy_async_cta() {
    asm volatile("fence.proxy.async.shared::cta;" ::: "memory");
}

// ---------------------------------------------------------------------------
// Single kernel. Blocks 0..31: fuse weights, release flag.
// Blocks 32..1055: TMA-bulk chunked gather of 276 rows -> smem sums ->
// acquire flag -> pipelined matvec vs g_Wf -> sigmoid -> out. 256 threads.
// ---------------------------------------------------------------------------
extern "C" __global__ __launch_bounds__(256) void graphsage_kernel(
    const float* __restrict__ embed,
    const float* __restrict__ W0,
    const float* __restrict__ b0,
    const float* __restrict__ W1,
    const int*   __restrict__ roots,
    const int*   __restrict__ idx1,
    const int*   __restrict__ idx2,
    float*       __restrict__ out)
{
    extern __shared__ __align__(16) char smem[];
    const int tid = threadIdx.x;

    if (blockIdx.x < FUSE_BLOCKS) {
        // ------------------ fuse path (proven form, dynamic smem) -----------
        float* sW1   = (float*)smem;             // 4 KB
        float* sRedF = (float*)(smem + 4096);    // 8 KB

        const int fb  = blockIdx.x;
        const int kk0 = fb * 8;

        {   // copy W0a rows (4 rows per block)
            const int base = fb * 512;
#pragma unroll
            for (int i = 0; i < 2; i++)
                g_Wf[base + tid + i * 256] = __ldg(&W0[base + tid + i * 256]);
        }
        for (int i = tid; i < 1024; i += 256)
            sW1[i] = __ldg(&W1[kk0 * 128 + i]);
        __syncthreads();

        const int g = tid >> 7;
        const int d = tid & 127;

        float acc[8];
#pragma unroll
        for (int rr = 0; rr < 8; rr++) acc[rr] = 0.f;

        const int jbeg = g * 64;
        for (int j = 0; j < 64; j += 4) {
            float wv[4];
#pragma unroll
            for (int u = 0; u < 4; u++)
                wv[u] = __ldg(&W0[(size_t)(128 + jbeg + j + u) * 128 + d]);
#pragma unroll
            for (int u = 0; u < 4; u++) {
#pragma unroll
                for (int rr = 0; rr < 8; rr++)
                    acc[rr] = fmaf(sW1[rr * 128 + jbeg + j + u], wv[u], acc[rr]);
            }
        }
#pragma unroll
        for (int rr = 0; rr < 8; rr++)
            sRedF[g * 1024 + rr * 128 + d] = acc[rr];
        __syncthreads();

        if (g == 0) {
#pragma unroll
            for (int rr = 0; rr < 8; rr++)
                g_Wf[(size_t)(128 + kk0 + rr) * 128 + d] =
                    sRedF[rr * 128 + d] + sRedF[1024 + rr * 128 + d];
        }
        __threadfence();          // release
        __syncthreads();
        if (tid == 0) atomicAdd(&g_flag, 1);
        return;
    }

    // ------------------ gather via TMA bulk + per-block MLP -----------------
    int*   sRows = (int*)(smem + OFF_ROWS);
    float* sAct  = (float*)(smem + OFF_ACT);
    float* sRedM = (float*)(smem + OFF_REDM);
    const uint32_t smem_base = smem_u32(smem);
    const uint32_t mbar0 = smem_base + OFF_MBAR;
    const uint32_t mbar1 = mbar0 + 8;

    const int b = blockIdx.x - FUSE_BLOCKS;    // 0..1023

    // Stage unified row-index table: [leaf 250][idx1 25][root 1]
    for (int i = tid; i < NPB; i += 256) sRows[i] = idx2[b * NPB + i];
    if (tid < N0) sRows[NPB + tid] = idx1[b * N0 + tid];
    if (tid == 64) sRows[275] = roots[b];
    if (tid == 0) { mbar_init(mbar0); mbar_init(mbar1); }
    __syncthreads();
    fence_proxy_async_cta();   // order barrier init + generic writes vs async proxy

    // Issue helper (tid 0 only): chunk c into buffer (c&1)
    auto issue_chunk = [&](int c) {
        const int base = c * CHUNK;
        const int nr   = (c == NCHG - 1) ? (ROWS_T - base) : CHUNK;
        const uint32_t mb  = (c & 1) ? mbar1 : mbar0;
        const uint32_t dst = smem_base + ((c & 1) ? OFF_BUF1 : OFF_BUF0);
        mbar_expect_tx(mb, (uint32_t)nr * 512u);
        for (int r = 0; r < nr; r++)
            tma_bulk_row(dst + r * 512,
                         (const void*)(embed + (size_t)sRows[base + r] * DIM),
                         mb);
    };

    if (tid == 0) { issue_chunk(0); issue_chunk(1); }

    const int h = tid >> 7;          // row-parity half
    const int d = tid & 127;         // dim
    float acc2 = 0.f;                // leaf sum
    float acc1 = 0.f;                // idx1 sum

    for (int c = 0; c < NCHG; c++) {
        const uint32_t mb = (c & 1) ? mbar1 : mbar0;
        mbar_wait(mb, (c >> 1) & 1);

        const float* bufF = (const float*)(smem + ((c & 1) ? OFF_BUF1 : OFF_BUF0));
        const int base = c * CHUNK;
        const int nr   = (c == NCHG - 1) ? (ROWS_T - base) : CHUNK;

        for (int r = h; r < nr; r += 2) {
            const int g = base + r;
            const float v = bufF[r * 128 + d];
            if (g < NPB)       acc2 += v;
            else if (g < 275)  acc1 += v;
            else               sAct[d] = v;     // root embedding
        }
        __syncthreads();                 // all reads of this buffer done
        if (tid == 0 && c + 2 < NCHG) {
            fence_proxy_async_cta();     // order prior generic reads vs TMA refill
            issue_chunk(c + 2);
        }
    }

    // Combine halves into activation vector
    sRedM[tid]       = acc2;
    sRedM[256 + tid] = acc1;
    __syncthreads();
    if (tid < 128) {
        sAct[256 + tid] = (sRedM[tid] + sRedM[128 + tid]) * (1.0f / 250.0f);
    } else {
        const int dd = tid - 128;
        sAct[128 + dd] = (sRedM[256 + dd] + sRedM[384 + dd]) * (1.0f / 25.0f);
    }

    // Acquire fused weights (fuse blocks are wave-1; typically zero wait)
    if (tid == 0) {
        while (atomicAdd(&g_flag, 0) < FUSE_DONE) {}
        __threadfence();
    }
    __syncthreads();

    // ------------------ per-block MLP (pipelined float4 weights) ------------
    // thread = (cg = tid&31 -> 4 output cols, kg = tid>>5 -> 48 k's).
    {
        const int cg = tid & 31;
        const int kg = tid >> 5;
        const int kbeg = kg * 48;
        const float* Wp = g_Wf + (size_t)kbeg * 128 + cg * 4;

        float4 acc = make_float4(0.f, 0.f, 0.f, 0.f);
        float4 wbuf[4];
#pragma unroll
        for (int u = 0; u < 4; u++)
            wbuf[u] = *(const float4*)(Wp + (size_t)u * 128);

        for (int k0 = 4; k0 < 48; k0 += 4) {
            float4 wn[4];
#pragma unroll
            for (int u = 0; u < 4; u++)
                wn[u] = *(const float4*)(Wp + (size_t)(k0 + u) * 128);
#pragma unroll
            for (int u = 0; u < 4; u++) {
                const float a = sAct[kbeg + k0 - 4 + u];
                acc.x = fmaf(a, wbuf[u].x, acc.x);
                acc.y = fmaf(a, wbuf[u].y, acc.y);
                acc.z = fmaf(a, wbuf[u].z, acc.z);
                acc.w = fmaf(a, wbuf[u].w, acc.w);
            }
#pragma unroll
            for (int u = 0; u < 4; u++) wbuf[u] = wn[u];
        }
#pragma unroll
        for (int u = 0; u < 4; u++) {
            const float a = sAct[kbeg + 44 + u];
            acc.x = fmaf(a, wbuf[u].x, acc.x);
            acc.y = fmaf(a, wbuf[u].y, acc.y);
            acc.z = fmaf(a, wbuf[u].z, acc.z);
            acc.w = fmaf(a, wbuf[u].w, acc.w);
        }
        __syncthreads();                 // sRedM scratch reuse
        *(float4*)&sRedM[kg * 128 + cg * 4] = acc;
    }
    __syncthreads();

    if (tid < 128) {
        float s = __ldg(&b0[tid]);
#pragma unroll
        for (int j = 0; j < 8; j++) s += sRedM[j * 128 + tid];
        out[(size_t)b * 128 + tid] = 1.0f / (1.0f + __expf(-s));
    }
}

// ---------------------------------------------------------------------------
// Inputs: embed_table, W0, b0, W1, roots, idx1, idx2
// ---------------------------------------------------------------------------
extern "C" void kernel_launch(void* const* d_in, const int* in_sizes, int n_in,
                              void* d_out, int out_size)
{
    const float* embed = (const float*)d_in[0];
    const float* W0    = (const float*)d_in[1];
    const float* b0    = (const float*)d_in[2];
    const float* W1    = (const float*)d_in[3];
    const int*   roots = (const int*)  d_in[4];
    const int*   idx1  = (const int*)  d_in[5];
    const int*   idx2  = (const int*)  d_in[6];
    float*       out   = (float*)d_out;

    static int attr_set = 0;
    if (!attr_set) {
        cudaFuncSetAttribute(graphsage_kernel,
                             cudaFuncAttributeMaxDynamicSharedMemorySize,
                             SMEM_BYTES);
        attr_set = 1;
    }

    graphsage_kernel<<<FUSE_BLOCKS + BATCH, 256, SMEM_BYTES>>>(
        embed, W0, b0, W1, roots, idx1, idx2, out);
}

// round 16
// speedup vs baseline: 1.3197x; 1.3197x over previous
#include <cuda_runtime.h>
#include <stdint.h>
#include <math.h>

#define BATCH 1024
#define DIM   128
#define N0    25
#define N1    10
#define NPB   250
#define FUSE_BLOCKS 32           // blocks 0..31 build g_Wf (8 product rows each)
#define FUSE_DONE FUSE_BLOCKS

// Fused weight: rows 0..127 = W0[0:128,:] ; rows 128..383 = W1 @ W0[128:256,:]
__device__ __align__(16) float g_Wf[384 * 128];
__device__ int g_flag;          // zero-init; monotonic across replays (benign: Wf replay-invariant)

// ---------------------------------------------------------------------------
// Single kernel. Blocks 0..31: fuse weights, release flag.
// Blocks 32..1055: software-pipelined gather of ONE batch row -> smem act ->
// acquire flag -> pipelined matvec vs g_Wf -> sigmoid -> out. 256 threads.
// __launch_bounds__(256, 6): cap regs so 6 blocks fit per SM (R14 was 4).
// ---------------------------------------------------------------------------
__global__ __launch_bounds__(256, 6) void graphsage_kernel(
    const float* __restrict__ embed,
    const float* __restrict__ W0,
    const float* __restrict__ b0,
    const float* __restrict__ W1,
    const int*   __restrict__ roots,
    const int*   __restrict__ idx1,
    const int*   __restrict__ idx2,
    float*       __restrict__ out)
{
    const int tid = threadIdx.x;

    if (blockIdx.x < FUSE_BLOCKS) {
        // ------------------ fuse path (proven form) ------------------
        __shared__ __align__(16) float sW1[8 * 128];
        __shared__ __align__(16) float sRedF[2 * 8 * 128];

        const int fb  = blockIdx.x;
        const int kk0 = fb * 8;

        {   // copy W0a rows (4 rows per block)
            const int base = fb * 512;
#pragma unroll
            for (int i = 0; i < 2; i++)
                g_Wf[base + tid + i * 256] = __ldg(&W0[base + tid + i * 256]);
        }

        for (int i = tid; i < 1024; i += 256)
            sW1[i] = __ldg(&W1[kk0 * 128 + i]);
        __syncthreads();

        const int g = tid >> 7;
        const int d = tid & 127;

        float acc[8];
#pragma unroll
        for (int rr = 0; rr < 8; rr++) acc[rr] = 0.f;

        const int jbeg = g * 64;
        for (int j = 0; j < 64; j += 4) {
            float wv[4];
#pragma unroll
            for (int u = 0; u < 4; u++)
                wv[u] = __ldg(&W0[(size_t)(128 + jbeg + j + u) * 128 + d]);
#pragma unroll
            for (int u = 0; u < 4; u++) {
#pragma unroll
                for (int rr = 0; rr < 8; rr++)
                    acc[rr] = fmaf(sW1[rr * 128 + jbeg + j + u], wv[u], acc[rr]);
            }
        }

#pragma unroll
        for (int rr = 0; rr < 8; rr++)
            sRedF[g * 1024 + rr * 128 + d] = acc[rr];
        __syncthreads();

        if (g == 0) {
#pragma unroll
            for (int rr = 0; rr < 8; rr++)
                g_Wf[(size_t)(128 + kk0 + rr) * 128 + d] =
                    sRedF[rr * 128 + d] + sRedF[1024 + rr * 128 + d];
        }
        __threadfence();          // release
        __syncthreads();
        if (tid == 0) atomicAdd(&g_flag, 1);
        return;
    }

    // ------------------ gather (one batch row) + per-block MLP ------------------
    __shared__ int   sIdx2[NPB];
    __shared__ int   sIdx1[N0];
    __shared__ __align__(16) float sRedA[8 * 128];
    __shared__ __align__(16) float sRedB[8 * 128];
    __shared__ __align__(16) float sAct[384];
    __shared__ __align__(16) float sRedM[8 * 128];   // kg partials [kg][col]

    const int b = blockIdx.x - FUSE_BLOCKS;   // 0..1023

    const int w = tid >> 5;          // warp 0..7
    const int l = tid & 31;          // lane
    const int e = l * 4;             // float4 offset in 128-dim row

    if (tid < NPB) sIdx2[tid] = idx2[b * NPB + tid];
    if (tid < N0)  sIdx1[tid] = idx1[b * N0 + tid];
    __syncthreads();

    const float* E = embed + e;

    // ---- leaf rows: software-pipelined batches of 4 (load i+1, consume i) ----
    float4 a2 = make_float4(0.f, 0.f, 0.f, 0.f);
    float4 buf[4];
#pragma unroll
    for (int u = 0; u < 4; u++) {
        const int rr = w + u * 8;
        if (rr < NPB) buf[u] = *(const float4*)(E + (size_t)sIdx2[rr] * DIM);
        else          buf[u] = make_float4(0.f, 0.f, 0.f, 0.f);
    }
    for (int r = w + 32; r < NPB; r += 32) {
        float4 nxt[4];
#pragma unroll
        for (int u = 0; u < 4; u++) {
            const int rr = r + u * 8;
            if (rr < NPB) nxt[u] = *(const float4*)(E + (size_t)sIdx2[rr] * DIM);
            else          nxt[u] = make_float4(0.f, 0.f, 0.f, 0.f);
        }
#pragma unroll
        for (int u = 0; u < 4; u++) {
            a2.x += buf[u].x; a2.y += buf[u].y; a2.z += buf[u].z; a2.w += buf[u].w;
        }
#pragma unroll
        for (int u = 0; u < 4; u++) buf[u] = nxt[u];
    }
#pragma unroll
    for (int u = 0; u < 4; u++) {
        a2.x += buf[u].x; a2.y += buf[u].y; a2.z += buf[u].z; a2.w += buf[u].w;
    }

    // ---- idx1 rows (few per warp) ----
    float4 a1 = make_float4(0.f, 0.f, 0.f, 0.f);
    for (int q = w; q < N0; q += 8) {
        const float4 v = *(const float4*)(E + (size_t)sIdx1[q] * DIM);
        a1.x += v.x; a1.y += v.y; a1.z += v.z; a1.w += v.w;
    }

    // root embedding straight into sAct
    if (w == 0) {
        const float4 h0 = *(const float4*)(E + (size_t)__ldg(&roots[b]) * DIM);
        *(float4*)&sAct[e] = h0;
    }

    *(float4*)&sRedA[w * 128 + e] = a2;
    *(float4*)&sRedB[w * 128 + e] = a1;
    __syncthreads();

    // finish means
    if (tid < 128) {
        float s = 0.f;
#pragma unroll
        for (int j = 0; j < 8; j++) s += sRedB[j * 128 + tid];
        sAct[128 + tid] = s * (1.0f / 25.0f);
    } else {
        const int dd = tid - 128;
        float s = 0.f;
#pragma unroll
        for (int j = 0; j < 8; j++) s += sRedA[j * 128 + dd];
        sAct[256 + dd] = s * (1.0f / 250.0f);
    }

    // acquire fused weights (fuse blocks are wave-1; typically zero wait)
    if (tid == 0) {
        while (atomicAdd(&g_flag, 0) < FUSE_DONE) {}
        __threadfence();          // acquire
    }
    __syncthreads();

    // ------------------ per-block MLP (pipelined weight loads) ------------------
    // thread = (cg = tid&31 -> 4 output cols, kg = tid>>5 -> 48 k's).
    {
        const int cg = tid & 31;
        const int kg = tid >> 5;
        const int kbeg = kg * 48;
        const float* Wp = g_Wf + (size_t)kbeg * 128 + cg * 4;

        float4 acc = make_float4(0.f, 0.f, 0.f, 0.f);
        float4 wbuf[4];
#pragma unroll
        for (int u = 0; u < 4; u++)
            wbuf[u] = *(const float4*)(Wp + (size_t)u * 128);

        for (int k0 = 4; k0 < 48; k0 += 4) {
            float4 wn[4];
#pragma unroll
            for (int u = 0; u < 4; u++)
                wn[u] = *(const float4*)(Wp + (size_t)(k0 + u) * 128);
#pragma unroll
            for (int u = 0; u < 4; u++) {
                const float a = sAct[kbeg + k0 - 4 + u];
                acc.x = fmaf(a, wbuf[u].x, acc.x);
                acc.y = fmaf(a, wbuf[u].y, acc.y);
                acc.z = fmaf(a, wbuf[u].z, acc.z);
                acc.w = fmaf(a, wbuf[u].w, acc.w);
            }
#pragma unroll
            for (int u = 0; u < 4; u++) wbuf[u] = wn[u];
        }
#pragma unroll
        for (int u = 0; u < 4; u++) {
            const float a = sAct[kbeg + 44 + u];
            acc.x = fmaf(a, wbuf[u].x, acc.x);
            acc.y = fmaf(a, wbuf[u].y, acc.y);
            acc.z = fmaf(a, wbuf[u].z, acc.z);
            acc.w = fmaf(a, wbuf[u].w, acc.w);
        }

        *(float4*)&sRedM[kg * 128 + cg * 4] = acc;
    }
    __syncthreads();

    if (tid < 128) {
        float s = __ldg(&b0[tid]);
#pragma unroll
        for (int j = 0; j < 8; j++) s += sRedM[j * 128 + tid];
        out[(size_t)b * 128 + tid] = 1.0f / (1.0f + __expf(-s));
    }
}

// ---------------------------------------------------------------------------
// Inputs: embed_table, W0, b0, W1, roots, idx1, idx2
// ---------------------------------------------------------------------------
extern "C" void kernel_launch(void* const* d_in, const int* in_sizes, int n_in,
                              void* d_out, int out_size)
{
    const float* embed = (const float*)d_in[0];
    const float* W0    = (const float*)d_in[1];
    const float* b0    = (const float*)d_in[2];
    const float* W1    = (const float*)d_in[3];
    const int*   roots = (const int*)  d_in[4];
    const int*   idx1  = (const int*)  d_in[5];
    const int*   idx2  = (const int*)  d_in[6];
    float*       out   = (float*)d_out;

    graphsage_kernel<<<FUSE_BLOCKS + BATCH, 256>>>(
        embed, W0, b0, W1, roots, idx1, idx2, out);
}

// round 17
// speedup vs baseline: 1.4384x; 1.0899x over previous
#include <cuda_runtime.h>
#include <stdint.h>
#include <math.h>

#define BATCH 1024
#define DIM   128
#define N0    25
#define N1    10
#define NPB   250
#define FUSE_BLOCKS 32           // blocks 0..31 of kernel 1 build g_Wf

// Fused weight: rows 0..127 = W0[0:128,:] ; rows 128..383 = W1 @ W0[128:256,:]
__device__ __align__(16) float g_Wf[384 * 128];
// Activations: g_act[b] = [h0 | mean_idx1 | mean_leaf]
__device__ __align__(16) float g_act[BATCH * 384];

// ---------------------------------------------------------------------------
// Kernel 1: blocks 0..31 fuse weights; blocks 32..1055 gather ONE batch row
// (software-pipelined, R14-proven) and write g_act. 256 threads.
// ---------------------------------------------------------------------------
__global__ __launch_bounds__(256) void gather_fuse_kernel(
    const float* __restrict__ embed,
    const float* __restrict__ W0,
    const float* __restrict__ W1,
    const int*   __restrict__ roots,
    const int*   __restrict__ idx1,
    const int*   __restrict__ idx2)
{
    const int tid = threadIdx.x;

    if (blockIdx.x < FUSE_BLOCKS) {
        // ------------------ fuse path (proven form) ------------------
        __shared__ __align__(16) float sW1[8 * 128];
        __shared__ __align__(16) float sRedF[2 * 8 * 128];

        const int fb  = blockIdx.x;
        const int kk0 = fb * 8;

        {   // copy W0a rows (4 rows per block)
            const int base = fb * 512;
#pragma unroll
            for (int i = 0; i < 2; i++)
                g_Wf[base + tid + i * 256] = __ldg(&W0[base + tid + i * 256]);
        }
        for (int i = tid; i < 1024; i += 256)
            sW1[i] = __ldg(&W1[kk0 * 128 + i]);
        __syncthreads();

        const int g = tid >> 7;
        const int d = tid & 127;

        float acc[8];
#pragma unroll
        for (int rr = 0; rr < 8; rr++) acc[rr] = 0.f;

        const int jbeg = g * 64;
        for (int j = 0; j < 64; j += 4) {
            float wv[4];
#pragma unroll
            for (int u = 0; u < 4; u++)
                wv[u] = __ldg(&W0[(size_t)(128 + jbeg + j + u) * 128 + d]);
#pragma unroll
            for (int u = 0; u < 4; u++) {
#pragma unroll
                for (int rr = 0; rr < 8; rr++)
                    acc[rr] = fmaf(sW1[rr * 128 + jbeg + j + u], wv[u], acc[rr]);
            }
        }
#pragma unroll
        for (int rr = 0; rr < 8; rr++)
            sRedF[g * 1024 + rr * 128 + d] = acc[rr];
        __syncthreads();

        if (g == 0) {
#pragma unroll
            for (int rr = 0; rr < 8; rr++)
                g_Wf[(size_t)(128 + kk0 + rr) * 128 + d] =
                    sRedF[rr * 128 + d] + sRedF[1024 + rr * 128 + d];
        }
        return;
    }

    // ------------------ gather (one batch row), R14-proven ------------------
    __shared__ int   sIdx2[NPB];
    __shared__ int   sIdx1[N0];
    __shared__ __align__(16) float sRedA[8 * 128];
    __shared__ __align__(16) float sRedB[8 * 128];

    const int b = blockIdx.x - FUSE_BLOCKS;   // 0..1023

    const int w = tid >> 5;          // warp 0..7
    const int l = tid & 31;          // lane
    const int e = l * 4;             // float4 offset in 128-dim row

    if (tid < NPB) sIdx2[tid] = idx2[b * NPB + tid];
    if (tid < N0)  sIdx1[tid] = idx1[b * N0 + tid];
    __syncthreads();

    const float* E = embed + e;

    // leaf rows: software-pipelined batches of 4 (load i+1, consume i)
    float4 a2 = make_float4(0.f, 0.f, 0.f, 0.f);
    float4 buf[4];
#pragma unroll
    for (int u = 0; u < 4; u++) {
        const int rr = w + u * 8;
        if (rr < NPB) buf[u] = *(const float4*)(E + (size_t)sIdx2[rr] * DIM);
        else          buf[u] = make_float4(0.f, 0.f, 0.f, 0.f);
    }
    for (int r = w + 32; r < NPB; r += 32) {
        float4 nxt[4];
#pragma unroll
        for (int u = 0; u < 4; u++) {
            const int rr = r + u * 8;
            if (rr < NPB) nxt[u] = *(const float4*)(E + (size_t)sIdx2[rr] * DIM);
            else          nxt[u] = make_float4(0.f, 0.f, 0.f, 0.f);
        }
#pragma unroll
        for (int u = 0; u < 4; u++) {
            a2.x += buf[u].x; a2.y += buf[u].y; a2.z += buf[u].z; a2.w += buf[u].w;
        }
#pragma unroll
        for (int u = 0; u < 4; u++) buf[u] = nxt[u];
    }
#pragma unroll
    for (int u = 0; u < 4; u++) {
        a2.x += buf[u].x; a2.y += buf[u].y; a2.z += buf[u].z; a2.w += buf[u].w;
    }

    // idx1 rows
    float4 a1 = make_float4(0.f, 0.f, 0.f, 0.f);
    for (int q = w; q < N0; q += 8) {
        const float4 v = *(const float4*)(E + (size_t)sIdx1[q] * DIM);
        a1.x += v.x; a1.y += v.y; a1.z += v.z; a1.w += v.w;
    }

    // root embedding straight to g_act
    if (w == 0) {
        const float4 h0 = *(const float4*)(E + (size_t)__ldg(&roots[b]) * DIM);
        *(float4*)&g_act[b * 384 + e] = h0;
    }

    *(float4*)&sRedA[w * 128 + e] = a2;
    *(float4*)&sRedB[w * 128 + e] = a1;
    __syncthreads();

    if (tid < 128) {
        float s = 0.f;
#pragma unroll
        for (int j = 0; j < 8; j++) s += sRedB[j * 128 + tid];
        g_act[b * 384 + 128 + tid] = s * (1.0f / 25.0f);
    } else {
        const int dd = tid - 128;
        float s = 0.f;
#pragma unroll
        for (int j = 0; j < 8; j++) s += sRedA[j * 128 + dd];
        g_act[b * 384 + 256 + dd] = s * (1.0f / 250.0f);
    }
}

// ---------------------------------------------------------------------------
// Kernel 2: out = sigmoid(g_act @ g_Wf + b0). 1024 blocks x 256 threads,
// ONE row per block -> ~7 blocks/SM share the 192KB weight table in L1.
// thread = (cg = tid&31 -> 4 output cols, kg = tid>>5 -> 48 k's), pipelined.
// ---------------------------------------------------------------------------
__global__ __launch_bounds__(256) void mlp_kernel(
    const float* __restrict__ b0,
    float*       __restrict__ out)
{
    __shared__ __align__(16) float sAct[384];
    __shared__ __align__(16) float sRedM[8 * 128];   // [kg][col]

    const int tid = threadIdx.x;
    const int b   = blockIdx.x;

    // stage activation vector (coalesced)
    if (tid < 128) sAct[tid] = g_act[b * 384 + tid];
    else if (tid < 256) sAct[tid] = g_act[b * 384 + tid];
    if (tid < 128) sAct[256 + tid] = g_act[b * 384 + 256 + tid];
    __syncthreads();

    {
        const int cg = tid & 31;
        const int kg = tid >> 5;
        const int kbeg = kg * 48;
        const float* Wp = g_Wf + (size_t)kbeg * 128 + cg * 4;

        float4 acc = make_float4(0.f, 0.f, 0.f, 0.f);
        float4 wbuf[4];
#pragma unroll
        for (int u = 0; u < 4; u++)
            wbuf[u] = *(const float4*)(Wp + (size_t)u * 128);

        for (int k0 = 4; k0 < 48; k0 += 4) {
            float4 wn[4];
#pragma unroll
            for (int u = 0; u < 4; u++)
                wn[u] = *(const float4*)(Wp + (size_t)(k0 + u) * 128);
#pragma unroll
            for (int u = 0; u < 4; u++) {
                const float a = sAct[kbeg + k0 - 4 + u];
                acc.x = fmaf(a, wbuf[u].x, acc.x);
                acc.y = fmaf(a, wbuf[u].y, acc.y);
                acc.z = fmaf(a, wbuf[u].z, acc.z);
                acc.w = fmaf(a, wbuf[u].w, acc.w);
            }
#pragma unroll
            for (int u = 0; u < 4; u++) wbuf[u] = wn[u];
        }
#pragma unroll
        for (int u = 0; u < 4; u++) {
            const float a = sAct[kbeg + 44 + u];
            acc.x = fmaf(a, wbuf[u].x, acc.x);
            acc.y = fmaf(a, wbuf[u].y, acc.y);
            acc.z = fmaf(a, wbuf[u].z, acc.z);
            acc.w = fmaf(a, wbuf[u].w, acc.w);
        }

        *(float4*)&sRedM[kg * 128 + cg * 4] = acc;
    }
    __syncthreads();

    if (tid < 128) {
        float s = __ldg(&b0[tid]);
#pragma unroll
        for (int j = 0; j < 8; j++) s += sRedM[j * 128 + tid];
        out[(size_t)b * 128 + tid] = 1.0f / (1.0f + __expf(-s));
    }
}

// ---------------------------------------------------------------------------
// Inputs: embed_table, W0, b0, W1, roots, idx1, idx2
// ---------------------------------------------------------------------------
extern "C" void kernel_launch(void* const* d_in, const int* in_sizes, int n_in,
                              void* d_out, int out_size)
{
    const float* embed = (const float*)d_in[0];
    const float* W0    = (const float*)d_in[1];
    const float* b0    = (const float*)d_in[2];
    const float* W1    = (const float*)d_in[3];
    const int*   roots = (const int*)  d_in[4];
    const int*   idx1  = (const int*)  d_in[5];
    const int*   idx2  = (const int*)  d_in[6];
    float*       out   = (float*)d_out;

    gather_fuse_kernel<<<FUSE_BLOCKS + BATCH, 256>>>(embed, W0, W1, roots, idx1, idx2);
    mlp_kernel<<<BATCH, 256>>>(b0, out);
}